// round 15
// baseline (speedup 1.0000x reference)
#include <cuda_runtime.h>
#include <math.h>

#define NN 50000
#define EE 1000000
#define BB 4
#define TT 12
#define F0 8
#define HH 32
#define NP (NN*BB)      /* 200000 (node,batch) pairs */
#define BH (BB*HH)      /* 128 elems per node for H-state props */

// ---------------- scratch (device globals; no allocations allowed) ----------
__device__ float g_deg[NN];
__device__ float g_dinv[NN];
__device__ float g_diag[NN];
__device__ int   g_cnt[NN];
__device__ int   g_rowptr[NN + 1];
__device__ int   g_wpos[NN];
__device__ int   g_src[EE];
__device__ float g_norm[EE];
__device__ int   g_ei64 = 1;      // static init; detect only lowers to 0 (monotone, deterministic)

// bf16 gather buffers (stored as u16; unpack = 16-bit shift, no cvt in hot loop)
// ids: 0=Xt(32w) 1=T1 2=T2 3=H0 4=H1 5=HR 6=U1 7=U2
__device__ __align__(16) unsigned short g_bXt[NN * 32];
__device__ __align__(16) unsigned short g_bT1[NN * BH];
__device__ __align__(16) unsigned short g_bT2[NN * BH];
__device__ __align__(16) unsigned short g_bH0[NN * BH];
__device__ __align__(16) unsigned short g_bH1[NN * BH];
__device__ __align__(16) unsigned short g_bHR[NN * BH];
__device__ __align__(16) unsigned short g_bU1[NN * BH];
__device__ __align__(16) unsigned short g_bU2[NN * BH];

// fp32 masters (GRU state recursion + head stay full precision)
__device__ __align__(16) float g_H0[NN * BH];
__device__ __align__(16) float g_H1[NN * BH];
__device__ __align__(16) float g_Z [NN * BH];
__device__ __align__(16) float g_gx[(size_t)NP * 96];
__device__ float g_mean[BB * HH];

__device__ __forceinline__ unsigned short* bbufp(int id) {
    switch (id) {
        case 0: return g_bXt;
        case 1: return g_bT1;
        case 2: return g_bT2;
        case 3: return g_bH0;
        case 4: return g_bH1;
        case 5: return g_bHR;
        case 6: return g_bU1;
        default: return g_bU2;
    }
}

// bf16 helpers (shift-based; alu-pipe only) -----------------------------------
__device__ __forceinline__ float bf2f(unsigned short u) {
    return __uint_as_float(((unsigned)u) << 16);
}
__device__ __forceinline__ unsigned short pack_b1(float x) {
    return (unsigned short)((__float_as_uint(x) + 0x8000u) >> 16);
}
__device__ __forceinline__ void fma_b4(float4& acc, float nm, uint2 u) {
    float e0 = __uint_as_float(u.x << 16);
    float e1 = __uint_as_float(u.x & 0xffff0000u);
    float e2 = __uint_as_float(u.y << 16);
    float e3 = __uint_as_float(u.y & 0xffff0000u);
    acc.x = fmaf(nm, e0, acc.x);
    acc.y = fmaf(nm, e1, acc.y);
    acc.z = fmaf(nm, e2, acc.z);
    acc.w = fmaf(nm, e3, acc.w);
}
__device__ __forceinline__ float4 unpack_b4(uint2 u) {
    return make_float4(__uint_as_float(u.x << 16),
                       __uint_as_float(u.x & 0xffff0000u),
                       __uint_as_float(u.y << 16),
                       __uint_as_float(u.y & 0xffff0000u));
}
__device__ __forceinline__ uint2 pack_b4(float4 a) {
    unsigned x0 = __float_as_uint(a.x) + 0x8000u;
    unsigned y0 = __float_as_uint(a.y) + 0x8000u;
    unsigned z0 = __float_as_uint(a.z) + 0x8000u;
    unsigned w0 = __float_as_uint(a.w) + 0x8000u;
    uint2 o;
    o.x = __byte_perm(x0, y0, 0x7632);
    o.y = __byte_perm(z0, w0, 0x7632);
    return o;
}

// ---------------- init: zero states/graph + dtype probe ----------------------
__global__ void k_init(const int* __restrict__ ei32) {
    int i = blockIdx.x * blockDim.x + threadIdx.x;
    if (i < NN * BH) {
        g_H0[i] = 0.f; g_H1[i] = 0.f;
        g_bH0[i] = 0; g_bH1[i] = 0;
    }
    if (i < NN) { g_deg[i] = 0.f; g_cnt[i] = 0; }
    if (i < 4096) {
        if (ei32[2 * i + 1] != 0) atomicExch(&g_ei64, 0);
    }
}

__device__ __forceinline__ int edge_id(const void* ei, int idx) {
    return g_ei64 ? (int)((const long long*)ei)[idx] : ((const int*)ei)[idx];
}

// ---------------- graph preprocessing ---------------------------------------
__global__ void k_degcnt(const void* __restrict__ ei, const float* __restrict__ w) {
    int e = blockIdx.x * blockDim.x + threadIdx.x;
    if (e < EE) {
        atomicAdd(&g_deg[edge_id(ei, e)], w[e]);
        atomicAdd(&g_cnt[edge_id(ei, EE + e)], 1);
    }
}

__global__ void k_scan() {   // exclusive scan of cnt -> rowptr/wpos, plus dinv/diag
    __shared__ int sh[1024];
    __shared__ int carry;
    int tid = threadIdx.x;
    if (tid == 0) carry = 0;
    __syncthreads();
    for (int base = 0; base < NN; base += 1024) {
        int idx = base + tid;
        if (idx < NN) {
            float d = g_deg[idx];
            if (d > 0.f) { g_dinv[idx] = rsqrtf(d); g_diag[idx] = 0.f; }
            else         { g_dinv[idx] = 0.f;       g_diag[idx] = -1.f; }
        }
        int v = (idx < NN) ? g_cnt[idx] : 0;
        sh[tid] = v;
        __syncthreads();
        for (int off = 1; off < 1024; off <<= 1) {
            int tv = (tid >= off) ? sh[tid - off] : 0;
            __syncthreads();
            sh[tid] += tv;
            __syncthreads();
        }
        int incl = sh[tid];
        int basec = carry;
        if (idx < NN) {
            int rp = basec + incl - v;
            g_rowptr[idx] = rp;
            g_wpos[idx] = rp;
        }
        __syncthreads();
        if (tid == 0) carry = basec + sh[1023];
        __syncthreads();
    }
    if (tid == 0) g_rowptr[NN] = EE;
}

__global__ void k_scatter(const void* __restrict__ ei, const float* __restrict__ w) {
    int e = blockIdx.x * blockDim.x + threadIdx.x;
    if (e >= EE) return;
    int r = edge_id(ei, e);
    int c = edge_id(ei, EE + e);
    int pos = atomicAdd(&g_wpos[c], 1);
    g_src[pos] = r;
    g_norm[pos] = -w[e] * g_dinv[r] * g_dinv[c];
}

// ---------------- layer-0 input transpose: [B,T,N,F0] -> bf16 [N, B*F0] ------
__global__ void k_transpose(const float* __restrict__ in, int t) {
    int idx = blockIdx.x * blockDim.x + threadIdx.x;   // over NN*32
    if (idx >= NN * 32) return;
    int n = idx >> 5;
    int r = idx & 31;
    int b = r >> 3;
    int f = r & 7;
    g_bXt[idx] = pack_b1(in[(((size_t)b * TT + t) * NN + n) * F0 + f]);
}

// ---------------- dual sparse prop (bf16 operands, fp32 accum) ---------------
template<int VX, bool CHEB2, int SX, int DX, int TX, int SH, int DH, int TH>
__global__ void __launch_bounds__(256) k_prop2() {
    const unsigned short* __restrict__ xx  = bbufp(SX);
    unsigned short* __restrict__ yx        = bbufp(DX);
    const unsigned short* __restrict__ t0x = bbufp(TX);
    const uint2* __restrict__ xh   = (const uint2*)bbufp(SH);
    uint2* __restrict__ yh         = (uint2*)bbufp(DH);
    const uint2* __restrict__ t0h  = (const uint2*)bbufp(TH);
    const uint2* xxu = (const uint2*)xx;

    int wid = (blockIdx.x * blockDim.x + threadIdx.x) >> 5;
    int lane = threadIdx.x & 31;
    if (wid >= NN) return;
    int n = wid;
    int s = g_rowptr[n], e = g_rowptr[n + 1];

    float accx = 0.f;
    float4 accx4 = make_float4(0.f, 0.f, 0.f, 0.f);
    float4 acch = make_float4(0.f, 0.f, 0.f, 0.f);

    int i = s;
    for (; i + 2 <= e; i += 2) {
        int s0 = g_src[i], s1 = g_src[i + 1];
        float n0 = g_norm[i], n1 = g_norm[i + 1];
        uint2 h0 = xh[s0 * 32 + lane];
        uint2 h1 = xh[s1 * 32 + lane];
        if (VX == 32) {
            float a = bf2f(xx[s0 * 32 + lane]);
            float b = bf2f(xx[s1 * 32 + lane]);
            accx = fmaf(n0, a, accx);
            accx = fmaf(n1, b, accx);
        } else {
            uint2 a = xxu[s0 * 32 + lane];
            uint2 b = xxu[s1 * 32 + lane];
            fma_b4(accx4, n0, a);
            fma_b4(accx4, n1, b);
        }
        fma_b4(acch, n0, h0);
        fma_b4(acch, n1, h1);
    }
    for (; i < e; i++) {
        int s0 = g_src[i];
        float n0 = g_norm[i];
        uint2 h0 = xh[s0 * 32 + lane];
        if (VX == 32) {
            accx = fmaf(n0, bf2f(xx[s0 * 32 + lane]), accx);
        } else {
            uint2 a = xxu[s0 * 32 + lane];
            fma_b4(accx4, n0, a);
        }
        fma_b4(acch, n0, h0);
    }
    float d = g_diag[n];
    {
        fma_b4(acch, d, xh[n * 32 + lane]);
        if (CHEB2) {
            float4 tv = unpack_b4(t0h[n * 32 + lane]);
            acch.x = 2.f * acch.x - tv.x;
            acch.y = 2.f * acch.y - tv.y;
            acch.z = 2.f * acch.z - tv.z;
            acch.w = 2.f * acch.w - tv.w;
        }
        yh[n * 32 + lane] = pack_b4(acch);
    }
    if (VX == 32) {
        accx = fmaf(d, bf2f(xx[n * 32 + lane]), accx);
        if (CHEB2) accx = 2.f * accx - bf2f(t0x[n * 32 + lane]);
        yx[n * 32 + lane] = pack_b1(accx);
    } else {
        fma_b4(accx4, d, xxu[n * 32 + lane]);
        if (CHEB2) {
            float4 tv = unpack_b4(((const uint2*)t0x)[n * 32 + lane]);
            accx4.x = 2.f * accx4.x - tv.x;
            accx4.y = 2.f * accx4.y - tv.y;
            accx4.z = 2.f * accx4.z - tv.z;
            accx4.w = 2.f * accx4.w - tv.w;
        }
        ((uint2*)yx)[n * 32 + lane] = pack_b4(accx4);
    }
}

// ---------------- single sparse prop (HR chain), bf16, unroll x4 -------------
template<bool CHEB2, int SRC, int DST, int T0ID>
__global__ void __launch_bounds__(256) k_prop() {
    const uint2* __restrict__ x  = (const uint2*)bbufp(SRC);
    uint2* __restrict__ y        = (uint2*)bbufp(DST);
    const uint2* __restrict__ t0 = (const uint2*)bbufp(T0ID);
    int wid = (blockIdx.x * blockDim.x + threadIdx.x) >> 5;
    int lane = threadIdx.x & 31;
    if (wid >= NN) return;
    int n = wid;
    int s = g_rowptr[n], e = g_rowptr[n + 1];
    float4 acc = make_float4(0.f, 0.f, 0.f, 0.f);
    int i = s;
    for (; i + 4 <= e; i += 4) {
        int s0 = g_src[i], s1 = g_src[i + 1], s2 = g_src[i + 2], s3 = g_src[i + 3];
        float n0 = g_norm[i], n1 = g_norm[i + 1], n2 = g_norm[i + 2], n3 = g_norm[i + 3];
        uint2 v0 = x[s0 * 32 + lane];
        uint2 v1 = x[s1 * 32 + lane];
        uint2 v2 = x[s2 * 32 + lane];
        uint2 v3 = x[s3 * 32 + lane];
        fma_b4(acc, n0, v0);
        fma_b4(acc, n1, v1);
        fma_b4(acc, n2, v2);
        fma_b4(acc, n3, v3);
    }
    for (; i < e; i++) {
        uint2 v = x[g_src[i] * 32 + lane];
        fma_b4(acc, g_norm[i], v);
    }
    fma_b4(acc, g_diag[n], x[n * 32 + lane]);
    if (CHEB2) {
        float4 tv = unpack_b4(t0[n * 32 + lane]);
        acc.x = 2.f * acc.x - tv.x;
        acc.y = 2.f * acc.y - tv.y;
        acc.z = 2.f * acc.z - tv.z;
        acc.w = 2.f * acc.w - tv.w;
    }
    y[n * 32 + lane] = pack_b4(acc);
}

// ================= einsum kernels: p=16 pairs/warp, float4-X, Ws-in-regs =====
// block = 128 thr = 4 warps = 64 pairs. grid = NP/64 = 3125.

// ---------------- gx = sum_k TXk @ Wx[g,k] + bx[g]  (3 gates) ----------------
template<int FIN, int T0ID, int T1ID, int T2ID>
__global__ void __launch_bounds__(128) k_gx(const float* __restrict__ W,   // [3][3][FIN][32]
                                            const float* __restrict__ bx) // [3][32]
{
    const unsigned short* __restrict__ T0 = bbufp(T0ID);
    const unsigned short* __restrict__ T1 = bbufp(T1ID);
    const unsigned short* __restrict__ T2 = bbufp(T2ID);
    __shared__ float Ws[9 * FIN * 32];
    __shared__ float Xs[3][64 * FIN];
    int tid = threadIdx.x;
    for (int i = tid; i < 9 * FIN * 32; i += 128) Ws[i] = W[i];
    int pb = blockIdx.x * 64;
    for (int i = tid; i < 64 * FIN; i += 128) {
        int idx = pb * FIN + i;
        Xs[0][i] = bf2f(T0[idx]);
        Xs[1][i] = bf2f(T1[idx]);
        Xs[2][i] = bf2f(T2[idx]);
    }
    __syncthreads();
    int wp = tid >> 5, lane = tid & 31;
    float a0[16], a1[16], a2[16];
#pragma unroll
    for (int p = 0; p < 16; p++) { a0[p] = bx[lane]; a1[p] = bx[32 + lane]; a2[p] = bx[64 + lane]; }
#pragma unroll 1
    for (int k = 0; k < 3; k++) {
#pragma unroll 1
        for (int i4 = 0; i4 < FIN / 4; i4++) {
            float w0[4], w1[4], w2[4];
#pragma unroll
            for (int ii = 0; ii < 4; ii++) {
                w0[ii] = Ws[((0 * 3 + k) * FIN + i4 * 4 + ii) * 32 + lane];
                w1[ii] = Ws[((1 * 3 + k) * FIN + i4 * 4 + ii) * 32 + lane];
                w2[ii] = Ws[((2 * 3 + k) * FIN + i4 * 4 + ii) * 32 + lane];
            }
#pragma unroll
            for (int p = 0; p < 16; p++) {
                float4 xv = *(const float4*)&Xs[k][(wp * 16 + p) * FIN + i4 * 4];
                a0[p] = fmaf(xv.x, w0[0], fmaf(xv.y, w0[1], fmaf(xv.z, w0[2], fmaf(xv.w, w0[3], a0[p]))));
                a1[p] = fmaf(xv.x, w1[0], fmaf(xv.y, w1[1], fmaf(xv.z, w1[2], fmaf(xv.w, w1[3], a1[p]))));
                a2[p] = fmaf(xv.x, w2[0], fmaf(xv.y, w2[1], fmaf(xv.z, w2[2], fmaf(xv.w, w2[3], a2[p]))));
            }
        }
    }
#pragma unroll
    for (int p = 0; p < 16; p++) {
        size_t pair = pb + wp * 16 + p;
        g_gx[pair * 96 + lane]      = a0[p];
        g_gx[pair * 96 + 32 + lane] = a1[p];
        g_gx[pair * 96 + 64 + lane] = a2[p];
    }
}

// ---------------- Z/R gates + H*R (H from fp32 master, TH from bf16) ---------
template<int M>   // 0 -> H0, 1 -> H1
__global__ void __launch_bounds__(128) k_gates(const float* __restrict__ Wh,  // [2][3][32][32]
                                               const float* __restrict__ bh)  // [2][32]
{
    const float* __restrict__ H = (M == 0) ? g_H0 : g_H1;
    __shared__ float Ws[6144];
    __shared__ float Xs[3][2048];
    int tid = threadIdx.x;
    for (int i = tid; i < 6144; i += 128) Ws[i] = Wh[i];
    int pb = blockIdx.x * 64;
    for (int i = tid; i < 2048; i += 128) {
        int idx = pb * 32 + i;
        Xs[0][i] = H[idx];
        Xs[1][i] = bf2f(g_bT1[idx]);
        Xs[2][i] = bf2f(g_bT2[idx]);
    }
    __syncthreads();
    int wp = tid >> 5, lane = tid & 31;
    float az[16], ar[16];
#pragma unroll
    for (int p = 0; p < 16; p++) { az[p] = bh[lane]; ar[p] = bh[32 + lane]; }
#pragma unroll 1
    for (int k = 0; k < 3; k++) {
#pragma unroll 1
        for (int i4 = 0; i4 < 8; i4++) {
            float w0[4], w1[4];
#pragma unroll
            for (int ii = 0; ii < 4; ii++) {
                w0[ii] = Ws[(k * 32 + i4 * 4 + ii) * 32 + lane];
                w1[ii] = Ws[3072 + (k * 32 + i4 * 4 + ii) * 32 + lane];
            }
#pragma unroll
            for (int p = 0; p < 16; p++) {
                float4 xv = *(const float4*)&Xs[k][(wp * 16 + p) * 32 + i4 * 4];
                az[p] = fmaf(xv.x, w0[0], fmaf(xv.y, w0[1], fmaf(xv.z, w0[2], fmaf(xv.w, w0[3], az[p]))));
                ar[p] = fmaf(xv.x, w1[0], fmaf(xv.y, w1[1], fmaf(xv.z, w1[2], fmaf(xv.w, w1[3], ar[p]))));
            }
        }
    }
#pragma unroll
    for (int p = 0; p < 16; p++) {
        size_t pair = pb + wp * 16 + p;
        float z = 1.f / (1.f + expf(-(g_gx[pair * 96 + lane] + az[p])));
        float r = 1.f / (1.f + expf(-(g_gx[pair * 96 + 32 + lane] + ar[p])));
        float hv = Xs[0][(wp * 16 + p) * 32 + lane];
        g_Z[pair * 32 + lane] = z;
        g_bHR[pair * 32 + lane] = pack_b1(hv * r);
    }
}

// ---------------- candidate + blend (fp32 master in place + bf16 shadow) -----
template<int M>   // 0 -> H0, 1 -> H1
__global__ void __launch_bounds__(128) k_final(const float* __restrict__ Wh2,  // [3][32][32]
                                               const float* __restrict__ bh2)  // [32]
{
    float* __restrict__ Hst = (M == 0) ? g_H0 : g_H1;
    unsigned short* __restrict__ Hsh = (M == 0) ? g_bH0 : g_bH1;
    __shared__ float Ws[3072];
    __shared__ float Xs[3][2048];
    int tid = threadIdx.x;
    for (int i = tid; i < 3072; i += 128) Ws[i] = Wh2[i];
    int pb = blockIdx.x * 64;
    for (int i = tid; i < 2048; i += 128) {
        int idx = pb * 32 + i;
        Xs[0][i] = bf2f(g_bHR[idx]);
        Xs[1][i] = bf2f(g_bT1[idx]);
        Xs[2][i] = bf2f(g_bT2[idx]);
    }
    __syncthreads();
    int wp = tid >> 5, lane = tid & 31;
    float acc[16];
#pragma unroll
    for (int p = 0; p < 16; p++) acc[p] = bh2[lane];
#pragma unroll 1
    for (int k = 0; k < 3; k++) {
#pragma unroll 1
        for (int i4 = 0; i4 < 8; i4++) {
            float w0[4];
#pragma unroll
            for (int ii = 0; ii < 4; ii++)
                w0[ii] = Ws[(k * 32 + i4 * 4 + ii) * 32 + lane];
#pragma unroll
            for (int p = 0; p < 16; p++) {
                float4 xv = *(const float4*)&Xs[k][(wp * 16 + p) * 32 + i4 * 4];
                acc[p] = fmaf(xv.x, w0[0], fmaf(xv.y, w0[1], fmaf(xv.z, w0[2], fmaf(xv.w, w0[3], acc[p]))));
            }
        }
    }
#pragma unroll
    for (int p = 0; p < 16; p++) {
        size_t pair = pb + wp * 16 + p;
        float ht = tanhf(g_gx[pair * 96 + 64 + lane] + acc[p]);
        float z = g_Z[pair * 32 + lane];
        float h = Hst[pair * 32 + lane];   // read own element, then overwrite
        float hn = z * h + (1.f - z) * ht;
        Hst[pair * 32 + lane] = hn;
        Hsh[pair * 32 + lane] = pack_b1(hn);
    }
}

// ---------------- output head (fp32 master) ----------------------------------
__global__ void k_head(const float* __restrict__ muW, const float* __restrict__ mub,
                       const float* __restrict__ sgW, const float* __restrict__ sgb,
                       float* __restrict__ out) {
    int gtid = blockIdx.x * blockDim.x + threadIdx.x;
    int pair = gtid >> 5, lane = gtid & 31;
    if (pair >= NP) return;
    float v = g_H1[pair * 32 + lane];
    float m0 = v * muW[lane * 2 + 0];
    float m1 = v * muW[lane * 2 + 1];
    float s0 = v * sgW[lane * 2 + 0];
    float s1 = v * sgW[lane * 2 + 1];
#pragma unroll
    for (int o = 16; o > 0; o >>= 1) {
        m0 += __shfl_xor_sync(0xffffffffu, m0, o);
        m1 += __shfl_xor_sync(0xffffffffu, m1, o);
        s0 += __shfl_xor_sync(0xffffffffu, s0, o);
        s1 += __shfl_xor_sync(0xffffffffu, s1, o);
    }
    if (lane == 0) {
        int n = pair >> 2, b = pair & 3;
        float mu0 = 1.f / (1.f + expf(-(m0 + mub[0])));
        float mu1 = 1.f / (1.f + expf(-(m1 + mub[1])));
        float x0 = s0 + sgb[0], x1 = s1 + sgb[1];
        float sg0 = (x0 > 20.f) ? x0 : log1pf(expf(x0));
        float sg1 = (x1 > 20.f) ? x1 : log1pf(expf(x1));
        size_t o0 = ((size_t)b * NN + n) * 2;
        out[o0] = mu0;
        out[o0 + 1] = mu1;
        out[2 * (size_t)NN * BB + o0] = sg0;
        out[2 * (size_t)NN * BB + o0 + 1] = sg1;
    }
}

__global__ void k_mean() {
    int b = blockIdx.x;
    int h = threadIdx.x & 31;
    int grp = threadIdx.x >> 5;      // 8 groups
    float s = 0.f;
    for (int n = grp; n < NN; n += 8) s += g_H1[(size_t)n * 128 + b * 32 + h];
    __shared__ float sh[8][32];
    sh[grp][h] = s;
    __syncthreads();
    if (grp == 0) {
#pragma unroll
        for (int r = 1; r < 8; r++) s += sh[r][h];
        g_mean[b * 32 + h] = s / (float)NN;
    }
}

__global__ void k_soft(float* __restrict__ out) {
    int b = threadIdx.x >> 5, h = threadIdx.x & 31;
    float v = g_mean[b * 32 + h];
    float m = v;
#pragma unroll
    for (int o = 16; o > 0; o >>= 1) m = fmaxf(m, __shfl_xor_sync(0xffffffffu, m, o));
    float e = expf(v - m);
    float s = e;
#pragma unroll
    for (int o = 16; o > 0; o >>= 1) s += __shfl_xor_sync(0xffffffffu, s, o);
    out[4 * (size_t)NN * BB + b * 32 + h] = e / s;
}

// ---------------- host orchestration (kernel launches ONLY) -------------------
extern "C" void kernel_launch(void* const* d_in, const int* in_sizes, int n_in,
                              void* d_out, int out_size) {
    const float* in_tensor = (const float*)d_in[0];
    const void*  edge_ix   = d_in[1];
    const float* edge_w    = (const float*)d_in[2];
    const float* Wx0 = (const float*)d_in[3];
    const float* Wh0 = (const float*)d_in[4];
    const float* bx0 = (const float*)d_in[5];
    const float* bh0 = (const float*)d_in[6];
    const float* Wx1 = (const float*)d_in[7];
    const float* Wh1 = (const float*)d_in[8];
    const float* bx1 = (const float*)d_in[9];
    const float* bh1 = (const float*)d_in[10];
    const float* muW = (const float*)d_in[11];
    const float* mub = (const float*)d_in[12];
    const float* sgW = (const float*)d_in[13];
    const float* sgb = (const float*)d_in[14];
    float* out = (float*)d_out;

    k_init<<<(NN * BH + 255) / 256, 256>>>((const int*)edge_ix);
    k_degcnt<<<(EE + 255) / 256, 256>>>(edge_ix, edge_w);
    k_scan<<<1, 1024>>>();
    k_scatter<<<(EE + 255) / 256, 256>>>(edge_ix, edge_w);

    const int PGRID = NN / 8;    // 6250 blocks * 256 thr = warp per node
    const int EG64  = NP / 64;   // 3125 blocks * 128 thr = 64 pairs/block

    // buffer ids: 0=Xt 1=T1 2=T2 3=H0 4=H1 5=HR 6=U1 7=U2
    for (int t = 0; t < TT; t++) {
        // ---- layer 0 (state H0, input Xt) ----
        k_transpose<<<(NN * 32 + 255) / 256, 256>>>(in_tensor, t);
        k_prop2<32, false, 0, 6, 0, 3, 1, 3><<<PGRID, 256>>>();   // Xt->U1 | H0->T1
        k_prop2<32, true,  6, 7, 0, 1, 2, 3><<<PGRID, 256>>>();   // U1->U2 (t0=Xt) | T1->T2 (t0=H0)
        k_gx<8, 0, 6, 7><<<EG64, 128>>>(Wx0, bx0);
        k_gates<0><<<EG64, 128>>>(Wh0, bh0);
        k_prop<false, 5, 1, 5><<<PGRID, 256>>>();                 // HR->T1
        k_prop<true,  1, 2, 5><<<PGRID, 256>>>();                 // T1->T2 (t0=HR)
        k_final<0><<<EG64, 128>>>(Wh0 + 2 * 3 * 32 * 32, bh0 + 64);

        // ---- layer 1 (state H1, input = freshly updated H0) ----
        k_prop2<128, false, 3, 6, 3, 4, 1, 4><<<PGRID, 256>>>();  // H0->U1 | H1->T1
        k_prop2<128, true,  6, 7, 3, 1, 2, 4><<<PGRID, 256>>>();  // U1->U2 (t0=H0) | T1->T2 (t0=H1)
        k_gx<32, 3, 6, 7><<<EG64, 128>>>(Wx1, bx1);
        k_gates<1><<<EG64, 128>>>(Wh1, bh1);
        k_prop<false, 5, 1, 5><<<PGRID, 256>>>();
        k_prop<true,  1, 2, 5><<<PGRID, 256>>>();
        k_final<1><<<EG64, 128>>>(Wh1 + 2 * 3 * 32 * 32, bh1 + 64);
    }

    k_head<<<NP / 8, 256>>>(muW, mub, sgW, sgb, out);
    k_mean<<<BB, 256>>>();
    k_soft<<<1, 128>>>(out);
}

// round 16
// speedup vs baseline: 1.0187x; 1.0187x over previous
#include <cuda_runtime.h>
#include <math.h>

#define NN 50000
#define EE 1000000
#define BB 4
#define TT 12
#define F0 8
#define HH 32
#define NP (NN*BB)      /* 200000 (node,batch) pairs */
#define BH (BB*HH)      /* 128 elems per node for H-state props */

// ---------------- scratch (device globals; no allocations allowed) ----------
__device__ float g_deg[NN];
__device__ float g_dinv[NN];
__device__ float g_diag[NN];
__device__ int   g_cnt[NN];
__device__ int   g_rowptr[NN + 1];
__device__ int   g_wpos[NN];
__device__ int   g_src[EE];
__device__ float g_norm[EE];
__device__ int   g_ei64 = 1;      // static init; detect only lowers to 0 (monotone, deterministic)

// bf16 gather buffers (stored as u16; unpack = 16-bit shift, no cvt in hot loop)
// ids: 0=Xt(32w) 1=T1 2=T2 3=H0 4=H1 5=HR 6=U1 7=U2
__device__ __align__(16) unsigned short g_bXt[NN * 32];
__device__ __align__(16) unsigned short g_bT1[NN * BH];
__device__ __align__(16) unsigned short g_bT2[NN * BH];
__device__ __align__(16) unsigned short g_bH0[NN * BH];
__device__ __align__(16) unsigned short g_bH1[NN * BH];
__device__ __align__(16) unsigned short g_bHR[NN * BH];
__device__ __align__(16) unsigned short g_bU1[NN * BH];
__device__ __align__(16) unsigned short g_bU2[NN * BH];

// fp32 masters (GRU state recursion + head stay full precision)
__device__ __align__(16) float g_H0[NN * BH];
__device__ __align__(16) float g_H1[NN * BH];
// bf16 intermediates (pre-activation / gate values; heavily damped)
__device__ __align__(16) unsigned short g_Z [NN * BH];
__device__ __align__(16) unsigned short g_gx[(size_t)NP * 96];
__device__ float g_mean[BB * HH];

__device__ __forceinline__ unsigned short* bbufp(int id) {
    switch (id) {
        case 0: return g_bXt;
        case 1: return g_bT1;
        case 2: return g_bT2;
        case 3: return g_bH0;
        case 4: return g_bH1;
        case 5: return g_bHR;
        case 6: return g_bU1;
        default: return g_bU2;
    }
}

// bf16 helpers (shift-based; alu-pipe only) -----------------------------------
__device__ __forceinline__ float bf2f(unsigned short u) {
    return __uint_as_float(((unsigned)u) << 16);
}
__device__ __forceinline__ unsigned short pack_b1(float x) {
    return (unsigned short)((__float_as_uint(x) + 0x8000u) >> 16);
}
__device__ __forceinline__ void fma_b4(float4& acc, float nm, uint2 u) {
    float e0 = __uint_as_float(u.x << 16);
    float e1 = __uint_as_float(u.x & 0xffff0000u);
    float e2 = __uint_as_float(u.y << 16);
    float e3 = __uint_as_float(u.y & 0xffff0000u);
    acc.x = fmaf(nm, e0, acc.x);
    acc.y = fmaf(nm, e1, acc.y);
    acc.z = fmaf(nm, e2, acc.z);
    acc.w = fmaf(nm, e3, acc.w);
}
__device__ __forceinline__ float4 unpack_b4(uint2 u) {
    return make_float4(__uint_as_float(u.x << 16),
                       __uint_as_float(u.x & 0xffff0000u),
                       __uint_as_float(u.y << 16),
                       __uint_as_float(u.y & 0xffff0000u));
}
__device__ __forceinline__ uint2 pack_b4(float4 a) {
    unsigned x0 = __float_as_uint(a.x) + 0x8000u;
    unsigned y0 = __float_as_uint(a.y) + 0x8000u;
    unsigned z0 = __float_as_uint(a.z) + 0x8000u;
    unsigned w0 = __float_as_uint(a.w) + 0x8000u;
    uint2 o;
    o.x = __byte_perm(x0, y0, 0x7632);
    o.y = __byte_perm(z0, w0, 0x7632);
    return o;
}

// ---------------- init: zero states/graph + dtype probe ----------------------
__global__ void k_init(const int* __restrict__ ei32) {
    int i = blockIdx.x * blockDim.x + threadIdx.x;
    if (i < NN * BH) {
        g_H0[i] = 0.f; g_H1[i] = 0.f;
        g_bH0[i] = 0; g_bH1[i] = 0;
    }
    if (i < NN) { g_deg[i] = 0.f; g_cnt[i] = 0; }
    if (i < 4096) {
        if (ei32[2 * i + 1] != 0) atomicExch(&g_ei64, 0);
    }
}

__device__ __forceinline__ int edge_id(const void* ei, int idx) {
    return g_ei64 ? (int)((const long long*)ei)[idx] : ((const int*)ei)[idx];
}

// ---------------- graph preprocessing ---------------------------------------
__global__ void k_degcnt(const void* __restrict__ ei, const float* __restrict__ w) {
    int e = blockIdx.x * blockDim.x + threadIdx.x;
    if (e < EE) {
        atomicAdd(&g_deg[edge_id(ei, e)], w[e]);
        atomicAdd(&g_cnt[edge_id(ei, EE + e)], 1);
    }
}

__global__ void k_scan() {   // exclusive scan of cnt -> rowptr/wpos, plus dinv/diag
    __shared__ int sh[1024];
    __shared__ int carry;
    int tid = threadIdx.x;
    if (tid == 0) carry = 0;
    __syncthreads();
    for (int base = 0; base < NN; base += 1024) {
        int idx = base + tid;
        if (idx < NN) {
            float d = g_deg[idx];
            if (d > 0.f) { g_dinv[idx] = rsqrtf(d); g_diag[idx] = 0.f; }
            else         { g_dinv[idx] = 0.f;       g_diag[idx] = -1.f; }
        }
        int v = (idx < NN) ? g_cnt[idx] : 0;
        sh[tid] = v;
        __syncthreads();
        for (int off = 1; off < 1024; off <<= 1) {
            int tv = (tid >= off) ? sh[tid - off] : 0;
            __syncthreads();
            sh[tid] += tv;
            __syncthreads();
        }
        int incl = sh[tid];
        int basec = carry;
        if (idx < NN) {
            int rp = basec + incl - v;
            g_rowptr[idx] = rp;
            g_wpos[idx] = rp;
        }
        __syncthreads();
        if (tid == 0) carry = basec + sh[1023];
        __syncthreads();
    }
    if (tid == 0) g_rowptr[NN] = EE;
}

__global__ void k_scatter(const void* __restrict__ ei, const float* __restrict__ w) {
    int e = blockIdx.x * blockDim.x + threadIdx.x;
    if (e >= EE) return;
    int r = edge_id(ei, e);
    int c = edge_id(ei, EE + e);
    int pos = atomicAdd(&g_wpos[c], 1);
    g_src[pos] = r;
    g_norm[pos] = -w[e] * g_dinv[r] * g_dinv[c];
}

// ---------------- layer-0 input transpose: [B,T,N,F0] -> bf16 [N, B*F0] ------
__global__ void k_transpose(const float* __restrict__ in, int t) {
    int idx = blockIdx.x * blockDim.x + threadIdx.x;   // over NN*32
    if (idx >= NN * 32) return;
    int n = idx >> 5;
    int r = idx & 31;
    int b = r >> 3;
    int f = r & 7;
    g_bXt[idx] = pack_b1(in[(((size_t)b * TT + t) * NN + n) * F0 + f]);
}

// ---------------- dual sparse prop (bf16, fp32 accum), GRID-STRIDE -----------
#define PBLK 592                      /* 4 blocks/SM * 148 SMs; single wave */
#define PWARPS (PBLK * 8)             /* 4736 warps */

template<int VX, bool CHEB2, int SX, int DX, int TX, int SH, int DH, int TH>
__global__ void __launch_bounds__(256) k_prop2() {
    const unsigned short* __restrict__ xx  = bbufp(SX);
    unsigned short* __restrict__ yx        = bbufp(DX);
    const unsigned short* __restrict__ t0x = bbufp(TX);
    const uint2* __restrict__ xh   = (const uint2*)bbufp(SH);
    uint2* __restrict__ yh         = (uint2*)bbufp(DH);
    const uint2* __restrict__ t0h  = (const uint2*)bbufp(TH);
    const uint2* xxu = (const uint2*)xx;

    int wid0 = (blockIdx.x * blockDim.x + threadIdx.x) >> 5;
    int lane = threadIdx.x & 31;

    for (int n = wid0; n < NN; n += PWARPS) {
        int s = g_rowptr[n], e = g_rowptr[n + 1];

        float accx = 0.f;
        float4 accx4 = make_float4(0.f, 0.f, 0.f, 0.f);
        float4 acch = make_float4(0.f, 0.f, 0.f, 0.f);

        int i = s;
        for (; i + 2 <= e; i += 2) {
            int s0 = g_src[i], s1 = g_src[i + 1];
            float n0 = g_norm[i], n1 = g_norm[i + 1];
            uint2 h0 = xh[s0 * 32 + lane];
            uint2 h1 = xh[s1 * 32 + lane];
            if (VX == 32) {
                float a = bf2f(xx[s0 * 32 + lane]);
                float b = bf2f(xx[s1 * 32 + lane]);
                accx = fmaf(n0, a, accx);
                accx = fmaf(n1, b, accx);
            } else {
                uint2 a = xxu[s0 * 32 + lane];
                uint2 b = xxu[s1 * 32 + lane];
                fma_b4(accx4, n0, a);
                fma_b4(accx4, n1, b);
            }
            fma_b4(acch, n0, h0);
            fma_b4(acch, n1, h1);
        }
        for (; i < e; i++) {
            int s0 = g_src[i];
            float n0 = g_norm[i];
            uint2 h0 = xh[s0 * 32 + lane];
            if (VX == 32) {
                accx = fmaf(n0, bf2f(xx[s0 * 32 + lane]), accx);
            } else {
                uint2 a = xxu[s0 * 32 + lane];
                fma_b4(accx4, n0, a);
            }
            fma_b4(acch, n0, h0);
        }
        float d = g_diag[n];
        {
            fma_b4(acch, d, xh[n * 32 + lane]);
            if (CHEB2) {
                float4 tv = unpack_b4(t0h[n * 32 + lane]);
                acch.x = 2.f * acch.x - tv.x;
                acch.y = 2.f * acch.y - tv.y;
                acch.z = 2.f * acch.z - tv.z;
                acch.w = 2.f * acch.w - tv.w;
            }
            yh[n * 32 + lane] = pack_b4(acch);
        }
        if (VX == 32) {
            accx = fmaf(d, bf2f(xx[n * 32 + lane]), accx);
            if (CHEB2) accx = 2.f * accx - bf2f(t0x[n * 32 + lane]);
            yx[n * 32 + lane] = pack_b1(accx);
        } else {
            fma_b4(accx4, d, xxu[n * 32 + lane]);
            if (CHEB2) {
                float4 tv = unpack_b4(((const uint2*)t0x)[n * 32 + lane]);
                accx4.x = 2.f * accx4.x - tv.x;
                accx4.y = 2.f * accx4.y - tv.y;
                accx4.z = 2.f * accx4.z - tv.z;
                accx4.w = 2.f * accx4.w - tv.w;
            }
            ((uint2*)yx)[n * 32 + lane] = pack_b4(accx4);
        }
    }
}

// ---------------- single sparse prop (HR chain), bf16, GRID-STRIDE ----------
template<bool CHEB2, int SRC, int DST, int T0ID>
__global__ void __launch_bounds__(256) k_prop() {
    const uint2* __restrict__ x  = (const uint2*)bbufp(SRC);
    uint2* __restrict__ y        = (uint2*)bbufp(DST);
    const uint2* __restrict__ t0 = (const uint2*)bbufp(T0ID);
    int wid0 = (blockIdx.x * blockDim.x + threadIdx.x) >> 5;
    int lane = threadIdx.x & 31;

    for (int n = wid0; n < NN; n += PWARPS) {
        int s = g_rowptr[n], e = g_rowptr[n + 1];
        float4 acc = make_float4(0.f, 0.f, 0.f, 0.f);
        int i = s;
        for (; i + 4 <= e; i += 4) {
            int s0 = g_src[i], s1 = g_src[i + 1], s2 = g_src[i + 2], s3 = g_src[i + 3];
            float n0 = g_norm[i], n1 = g_norm[i + 1], n2 = g_norm[i + 2], n3 = g_norm[i + 3];
            uint2 v0 = x[s0 * 32 + lane];
            uint2 v1 = x[s1 * 32 + lane];
            uint2 v2 = x[s2 * 32 + lane];
            uint2 v3 = x[s3 * 32 + lane];
            fma_b4(acc, n0, v0);
            fma_b4(acc, n1, v1);
            fma_b4(acc, n2, v2);
            fma_b4(acc, n3, v3);
        }
        for (; i < e; i++) {
            uint2 v = x[g_src[i] * 32 + lane];
            fma_b4(acc, g_norm[i], v);
        }
        fma_b4(acc, g_diag[n], x[n * 32 + lane]);
        if (CHEB2) {
            float4 tv = unpack_b4(t0[n * 32 + lane]);
            acc.x = 2.f * acc.x - tv.x;
            acc.y = 2.f * acc.y - tv.y;
            acc.z = 2.f * acc.z - tv.z;
            acc.w = 2.f * acc.w - tv.w;
        }
        y[n * 32 + lane] = pack_b4(acc);
    }
}

// ================= einsums: R14 shape (p=4/warp, 16 pairs/block) =============

// ---------------- gx = sum_k TXk @ Wx[g,k] + bx[g]  (3 gates) ----------------
template<int FIN, int T0ID, int T1ID, int T2ID>
__global__ void k_gx(const float* __restrict__ W,   // [3][3][FIN][32]
                     const float* __restrict__ bx)  // [3][32]
{
    const unsigned short* __restrict__ T0 = bbufp(T0ID);
    const unsigned short* __restrict__ T1 = bbufp(T1ID);
    const unsigned short* __restrict__ T2 = bbufp(T2ID);
    __shared__ float Ws[9 * FIN * 32];
    __shared__ float Xs[3][16 * FIN];
    int tid = threadIdx.x;
    for (int i = tid; i < 9 * FIN * 32; i += 128) Ws[i] = W[i];
    int pb = blockIdx.x * 16;
    for (int i = tid; i < 16 * FIN; i += 128) {
        int idx = pb * FIN + i;
        Xs[0][i] = bf2f(T0[idx]);
        Xs[1][i] = bf2f(T1[idx]);
        Xs[2][i] = bf2f(T2[idx]);
    }
    __syncthreads();
    int warp = tid >> 5, lane = tid & 31;
    float a0[4], a1[4], a2[4];
#pragma unroll
    for (int p = 0; p < 4; p++) { a0[p] = bx[lane]; a1[p] = bx[32 + lane]; a2[p] = bx[64 + lane]; }
#pragma unroll
    for (int k = 0; k < 3; k++) {
#pragma unroll 4
        for (int i = 0; i < FIN; i++) {
            float w0 = Ws[((0 * 3 + k) * FIN + i) * 32 + lane];
            float w1 = Ws[((1 * 3 + k) * FIN + i) * 32 + lane];
            float w2 = Ws[((2 * 3 + k) * FIN + i) * 32 + lane];
#pragma unroll
            for (int p = 0; p < 4; p++) {
                float xv = Xs[k][(warp * 4 + p) * FIN + i];
                a0[p] = fmaf(xv, w0, a0[p]);
                a1[p] = fmaf(xv, w1, a1[p]);
                a2[p] = fmaf(xv, w2, a2[p]);
            }
        }
    }
#pragma unroll
    for (int p = 0; p < 4; p++) {
        size_t pair = pb + warp * 4 + p;
        g_gx[pair * 96 + lane]      = pack_b1(a0[p]);
        g_gx[pair * 96 + 32 + lane] = pack_b1(a1[p]);
        g_gx[pair * 96 + 64 + lane] = pack_b1(a2[p]);
    }
}

// ---------------- Z/R gates + H*R (H from fp32 master, TH from bf16) ---------
template<int M>   // 0 -> H0, 1 -> H1
__global__ void k_gates(const float* __restrict__ Wh,  // [2][3][32][32]
                        const float* __restrict__ bh)  // [2][32]
{
    const float* __restrict__ H = (M == 0) ? g_H0 : g_H1;
    __shared__ float Ws[6144];
    __shared__ float Xs[3][512];
    int tid = threadIdx.x;
    for (int i = tid; i < 6144; i += 128) Ws[i] = Wh[i];
    int pb = blockIdx.x * 16;
    for (int i = tid; i < 512; i += 128) {
        int idx = pb * 32 + i;
        Xs[0][i] = H[idx];
        Xs[1][i] = bf2f(g_bT1[idx]);
        Xs[2][i] = bf2f(g_bT2[idx]);
    }
    __syncthreads();
    int warp = tid >> 5, lane = tid & 31;
    float az[4], ar[4];
#pragma unroll
    for (int p = 0; p < 4; p++) { az[p] = bh[lane]; ar[p] = bh[32 + lane]; }
#pragma unroll
    for (int k = 0; k < 3; k++) {
#pragma unroll 4
        for (int i = 0; i < 32; i++) {
            float w0 = Ws[(k * 32 + i) * 32 + lane];
            float w1 = Ws[3072 + (k * 32 + i) * 32 + lane];
#pragma unroll
            for (int p = 0; p < 4; p++) {
                float xv = Xs[k][(warp * 4 + p) * 32 + i];
                az[p] = fmaf(xv, w0, az[p]);
                ar[p] = fmaf(xv, w1, ar[p]);
            }
        }
    }
#pragma unroll
    for (int p = 0; p < 4; p++) {
        size_t pair = pb + warp * 4 + p;
        float z = 1.f / (1.f + expf(-(bf2f(g_gx[pair * 96 + lane]) + az[p])));
        float r = 1.f / (1.f + expf(-(bf2f(g_gx[pair * 96 + 32 + lane]) + ar[p])));
        float hv = Xs[0][(warp * 4 + p) * 32 + lane];
        g_Z[pair * 32 + lane] = pack_b1(z);
        g_bHR[pair * 32 + lane] = pack_b1(hv * r);
    }
}

// ---------------- candidate + blend (fp32 master in place + bf16 shadow) -----
template<int M>   // 0 -> H0, 1 -> H1
__global__ void k_final(const float* __restrict__ Wh2,  // [3][32][32]
                        const float* __restrict__ bh2)  // [32]
{
    float* __restrict__ Hst = (M == 0) ? g_H0 : g_H1;
    unsigned short* __restrict__ Hsh = (M == 0) ? g_bH0 : g_bH1;
    __shared__ float Ws[3072];
    __shared__ float Xs[3][512];
    int tid = threadIdx.x;
    for (int i = tid; i < 3072; i += 128) Ws[i] = Wh2[i];
    int pb = blockIdx.x * 16;
    for (int i = tid; i < 512; i += 128) {
        int idx = pb * 32 + i;
        Xs[0][i] = bf2f(g_bHR[idx]);
        Xs[1][i] = bf2f(g_bT1[idx]);
        Xs[2][i] = bf2f(g_bT2[idx]);
    }
    __syncthreads();
    int warp = tid >> 5, lane = tid & 31;
    float acc[4];
#pragma unroll
    for (int p = 0; p < 4; p++) acc[p] = bh2[lane];
#pragma unroll
    for (int k = 0; k < 3; k++) {
#pragma unroll 4
        for (int i = 0; i < 32; i++) {
            float w = Ws[(k * 32 + i) * 32 + lane];
#pragma unroll
            for (int p = 0; p < 4; p++) {
                float xv = Xs[k][(warp * 4 + p) * 32 + i];
                acc[p] = fmaf(xv, w, acc[p]);
            }
        }
    }
#pragma unroll
    for (int p = 0; p < 4; p++) {
        size_t pair = pb + warp * 4 + p;
        float ht = tanhf(bf2f(g_gx[pair * 96 + 64 + lane]) + acc[p]);
        float z = bf2f(g_Z[pair * 32 + lane]);
        float h = Hst[pair * 32 + lane];   // read own element, then overwrite
        float hn = z * h + (1.f - z) * ht;
        Hst[pair * 32 + lane] = hn;
        Hsh[pair * 32 + lane] = pack_b1(hn);
    }
}

// ---------------- output head (fp32 master) ----------------------------------
__global__ void k_head(const float* __restrict__ muW, const float* __restrict__ mub,
                       const float* __restrict__ sgW, const float* __restrict__ sgb,
                       float* __restrict__ out) {
    int gtid = blockIdx.x * blockDim.x + threadIdx.x;
    int pair = gtid >> 5, lane = gtid & 31;
    if (pair >= NP) return;
    float v = g_H1[pair * 32 + lane];
    float m0 = v * muW[lane * 2 + 0];
    float m1 = v * muW[lane * 2 + 1];
    float s0 = v * sgW[lane * 2 + 0];
    float s1 = v * sgW[lane * 2 + 1];
#pragma unroll
    for (int o = 16; o > 0; o >>= 1) {
        m0 += __shfl_xor_sync(0xffffffffu, m0, o);
        m1 += __shfl_xor_sync(0xffffffffu, m1, o);
        s0 += __shfl_xor_sync(0xffffffffu, s0, o);
        s1 += __shfl_xor_sync(0xffffffffu, s1, o);
    }
    if (lane == 0) {
        int n = pair >> 2, b = pair & 3;
        float mu0 = 1.f / (1.f + expf(-(m0 + mub[0])));
        float mu1 = 1.f / (1.f + expf(-(m1 + mub[1])));
        float x0 = s0 + sgb[0], x1 = s1 + sgb[1];
        float sg0 = (x0 > 20.f) ? x0 : log1pf(expf(x0));
        float sg1 = (x1 > 20.f) ? x1 : log1pf(expf(x1));
        size_t o0 = ((size_t)b * NN + n) * 2;
        out[o0] = mu0;
        out[o0 + 1] = mu1;
        out[2 * (size_t)NN * BB + o0] = sg0;
        out[2 * (size_t)NN * BB + o0 + 1] = sg1;
    }
}

__global__ void k_mean() {
    int b = blockIdx.x;
    int h = threadIdx.x & 31;
    int grp = threadIdx.x >> 5;      // 8 groups
    float s = 0.f;
    for (int n = grp; n < NN; n += 8) s += g_H1[(size_t)n * 128 + b * 32 + h];
    __shared__ float sh[8][32];
    sh[grp][h] = s;
    __syncthreads();
    if (grp == 0) {
#pragma unroll
        for (int r = 1; r < 8; r++) s += sh[r][h];
        g_mean[b * 32 + h] = s / (float)NN;
    }
}

__global__ void k_soft(float* __restrict__ out) {
    int b = threadIdx.x >> 5, h = threadIdx.x & 31;
    float v = g_mean[b * 32 + h];
    float m = v;
#pragma unroll
    for (int o = 16; o > 0; o >>= 1) m = fmaxf(m, __shfl_xor_sync(0xffffffffu, m, o));
    float e = expf(v - m);
    float s = e;
#pragma unroll
    for (int o = 16; o > 0; o >>= 1) s += __shfl_xor_sync(0xffffffffu, s, o);
    out[4 * (size_t)NN * BB + b * 32 + h] = e / s;
}

// ---------------- host orchestration (kernel launches ONLY) -------------------
extern "C" void kernel_launch(void* const* d_in, const int* in_sizes, int n_in,
                              void* d_out, int out_size) {
    const float* in_tensor = (const float*)d_in[0];
    const void*  edge_ix   = d_in[1];
    const float* edge_w    = (const float*)d_in[2];
    const float* Wx0 = (const float*)d_in[3];
    const float* Wh0 = (const float*)d_in[4];
    const float* bx0 = (const float*)d_in[5];
    const float* bh0 = (const float*)d_in[6];
    const float* Wx1 = (const float*)d_in[7];
    const float* Wh1 = (const float*)d_in[8];
    const float* bx1 = (const float*)d_in[9];
    const float* bh1 = (const float*)d_in[10];
    const float* muW = (const float*)d_in[11];
    const float* mub = (const float*)d_in[12];
    const float* sgW = (const float*)d_in[13];
    const float* sgb = (const float*)d_in[14];
    float* out = (float*)d_out;

    k_init<<<(NN * BH + 255) / 256, 256>>>((const int*)edge_ix);
    k_degcnt<<<(EE + 255) / 256, 256>>>(edge_ix, edge_w);
    k_scan<<<1, 1024>>>();
    k_scatter<<<(EE + 255) / 256, 256>>>(edge_ix, edge_w);

    const int EGRID = NP / 16;   // 12500 blocks * 128 thr = 16 pairs/block

    // buffer ids: 0=Xt 1=T1 2=T2 3=H0 4=H1 5=HR 6=U1 7=U2
    for (int t = 0; t < TT; t++) {
        // ---- layer 0 (state H0, input Xt) ----
        k_transpose<<<(NN * 32 + 255) / 256, 256>>>(in_tensor, t);
        k_prop2<32, false, 0, 6, 0, 3, 1, 3><<<PBLK, 256>>>();   // Xt->U1 | H0->T1
        k_prop2<32, true,  6, 7, 0, 1, 2, 3><<<PBLK, 256>>>();   // U1->U2 (t0=Xt) | T1->T2 (t0=H0)
        k_gx<8, 0, 6, 7><<<EGRID, 128>>>(Wx0, bx0);
        k_gates<0><<<EGRID, 128>>>(Wh0, bh0);
        k_prop<false, 5, 1, 5><<<PBLK, 256>>>();                 // HR->T1
        k_prop<true,  1, 2, 5><<<PBLK, 256>>>();                 // T1->T2 (t0=HR)
        k_final<0><<<EGRID, 128>>>(Wh0 + 2 * 3 * 32 * 32, bh0 + 64);

        // ---- layer 1 (state H1, input = freshly updated H0) ----
        k_prop2<128, false, 3, 6, 3, 4, 1, 4><<<PBLK, 256>>>();  // H0->U1 | H1->T1
        k_prop2<128, true,  6, 7, 3, 1, 2, 4><<<PBLK, 256>>>();  // U1->U2 (t0=H0) | T1->T2 (t0=H1)
        k_gx<32, 3, 6, 7><<<EGRID, 128>>>(Wx1, bx1);
        k_gates<1><<<EGRID, 128>>>(Wh1, bh1);
        k_prop<false, 5, 1, 5><<<PBLK, 256>>>();
        k_prop<true,  1, 2, 5><<<PBLK, 256>>>();
        k_final<1><<<EGRID, 128>>>(Wh1 + 2 * 3 * 32 * 32, bh1 + 64);
    }

    k_head<<<NP / 8, 256>>>(muW, mub, sgW, sgb, out);
    k_mean<<<BB, 256>>>();
    k_soft<<<1, 128>>>(out);
}

// round 17
// speedup vs baseline: 1.0913x; 1.0713x over previous
#include <cuda_runtime.h>
#include <math.h>

#define NN 50000
#define EE 1000000
#define BB 4
#define TT 12
#define F0 8
#define HH 32
#define NP (NN*BB)      /* 200000 (node,batch) pairs */
#define BH (BB*HH)      /* 128 elems per node for H-state props */

// ---------------- scratch (device globals; no allocations allowed) ----------
__device__ float g_deg[NN];
__device__ float g_dinv[NN];
__device__ float g_diag[NN];
__device__ int   g_cnt[NN];
__device__ int   g_rowptr[NN + 1];
__device__ int   g_wpos[NN];
__device__ int   g_src[EE];
__device__ float g_norm[EE];
__device__ int   g_ei64 = 1;      // static init; detect only lowers to 0 (monotone, deterministic)

// bf16 gather buffers (u16 storage; unpack = 16-bit shift, no cvt in hot loop)
// ids: 0=Xt(32w) 1=T1 2=T2 3=H0 4=H1 5=HR 6=U1 7=U2 8=XA(32w) 9=XB(32w)
__device__ __align__(16) unsigned short g_bXt[NN * 32];
__device__ __align__(16) unsigned short g_bT1[NN * BH];
__device__ __align__(16) unsigned short g_bT2[NN * BH];
__device__ __align__(16) unsigned short g_bH0[NN * BH];
__device__ __align__(16) unsigned short g_bH1[NN * BH];
__device__ __align__(16) unsigned short g_bHR[NN * BH];
__device__ __align__(16) unsigned short g_bU1[NN * BH];
__device__ __align__(16) unsigned short g_bU2[NN * BH];
__device__ __align__(16) unsigned short g_bXA[NN * 32];
__device__ __align__(16) unsigned short g_bXB[NN * 32];

// fp32 masters (GRU state recursion + head stay full precision)
__device__ __align__(16) float g_H0[NN * BH];
__device__ __align__(16) float g_H1[NN * BH];
__device__ __align__(16) float g_Z [NN * BH];
__device__ __align__(16) float g_gx[(size_t)NP * 96];
__device__ float g_mean[BB * HH];

__device__ __forceinline__ unsigned short* bbufp(int id) {
    switch (id) {
        case 0: return g_bXt;
        case 1: return g_bT1;
        case 2: return g_bT2;
        case 3: return g_bH0;
        case 4: return g_bH1;
        case 5: return g_bHR;
        case 6: return g_bU1;
        case 7: return g_bU2;
        case 8: return g_bXA;
        default: return g_bXB;
    }
}

// bf16 helpers (shift-based; alu-pipe only) -----------------------------------
__device__ __forceinline__ float bf2f(unsigned short u) {
    return __uint_as_float(((unsigned)u) << 16);
}
__device__ __forceinline__ unsigned short pack_b1(float x) {
    return (unsigned short)((__float_as_uint(x) + 0x8000u) >> 16);
}
__device__ __forceinline__ void fma_b4(float4& acc, float nm, uint2 u) {
    float e0 = __uint_as_float(u.x << 16);
    float e1 = __uint_as_float(u.x & 0xffff0000u);
    float e2 = __uint_as_float(u.y << 16);
    float e3 = __uint_as_float(u.y & 0xffff0000u);
    acc.x = fmaf(nm, e0, acc.x);
    acc.y = fmaf(nm, e1, acc.y);
    acc.z = fmaf(nm, e2, acc.z);
    acc.w = fmaf(nm, e3, acc.w);
}
__device__ __forceinline__ float4 unpack_b4(uint2 u) {
    return make_float4(__uint_as_float(u.x << 16),
                       __uint_as_float(u.x & 0xffff0000u),
                       __uint_as_float(u.y << 16),
                       __uint_as_float(u.y & 0xffff0000u));
}
__device__ __forceinline__ uint2 pack_b4(float4 a) {
    unsigned x0 = __float_as_uint(a.x) + 0x8000u;
    unsigned y0 = __float_as_uint(a.y) + 0x8000u;
    unsigned z0 = __float_as_uint(a.z) + 0x8000u;
    unsigned w0 = __float_as_uint(a.w) + 0x8000u;
    uint2 o;
    o.x = __byte_perm(x0, y0, 0x7632);
    o.y = __byte_perm(z0, w0, 0x7632);
    return o;
}

// ---------------- init: zero states/graph/U-basis + dtype probe ---------------
__global__ void k_init(const int* __restrict__ ei32) {
    int i = blockIdx.x * blockDim.x + threadIdx.x;
    if (i < NN * BH) {
        g_H0[i] = 0.f; g_H1[i] = 0.f;
        g_bH0[i] = 0; g_bH1[i] = 0;
        g_bU1[i] = 0; g_bU2[i] = 0;   // basis(H0=0)=0 for t=0 layer-0 gates
    }
    if (i < NN) { g_deg[i] = 0.f; g_cnt[i] = 0; }
    if (i < 4096) {
        if (ei32[2 * i + 1] != 0) atomicExch(&g_ei64, 0);
    }
}

__device__ __forceinline__ int edge_id(const void* ei, int idx) {
    return g_ei64 ? (int)((const long long*)ei)[idx] : ((const int*)ei)[idx];
}

// ---------------- graph preprocessing ---------------------------------------
__global__ void k_degcnt(const void* __restrict__ ei, const float* __restrict__ w) {
    int e = blockIdx.x * blockDim.x + threadIdx.x;
    if (e < EE) {
        atomicAdd(&g_deg[edge_id(ei, e)], w[e]);
        atomicAdd(&g_cnt[edge_id(ei, EE + e)], 1);
    }
}

__global__ void k_scan() {   // exclusive scan of cnt -> rowptr/wpos, plus dinv/diag
    __shared__ int sh[1024];
    __shared__ int carry;
    int tid = threadIdx.x;
    if (tid == 0) carry = 0;
    __syncthreads();
    for (int base = 0; base < NN; base += 1024) {
        int idx = base + tid;
        if (idx < NN) {
            float d = g_deg[idx];
            if (d > 0.f) { g_dinv[idx] = rsqrtf(d); g_diag[idx] = 0.f; }
            else         { g_dinv[idx] = 0.f;       g_diag[idx] = -1.f; }
        }
        int v = (idx < NN) ? g_cnt[idx] : 0;
        sh[tid] = v;
        __syncthreads();
        for (int off = 1; off < 1024; off <<= 1) {
            int tv = (tid >= off) ? sh[tid - off] : 0;
            __syncthreads();
            sh[tid] += tv;
            __syncthreads();
        }
        int incl = sh[tid];
        int basec = carry;
        if (idx < NN) {
            int rp = basec + incl - v;
            g_rowptr[idx] = rp;
            g_wpos[idx] = rp;
        }
        __syncthreads();
        if (tid == 0) carry = basec + sh[1023];
        __syncthreads();
    }
    if (tid == 0) g_rowptr[NN] = EE;
}

__global__ void k_scatter(const void* __restrict__ ei, const float* __restrict__ w) {
    int e = blockIdx.x * blockDim.x + threadIdx.x;
    if (e >= EE) return;
    int r = edge_id(ei, e);
    int c = edge_id(ei, EE + e);
    int pos = atomicAdd(&g_wpos[c], 1);
    g_src[pos] = r;
    g_norm[pos] = -w[e] * g_dinv[r] * g_dinv[c];
}

// ---------------- layer-0 input transpose: [B,T,N,F0] -> bf16 [N, B*F0] ------
__global__ void k_transpose(const float* __restrict__ in, int t) {
    int idx = blockIdx.x * blockDim.x + threadIdx.x;   // over NN*32
    if (idx >= NN * 32) return;
    int n = idx >> 5;
    int r = idx & 31;
    int b = r >> 3;
    int f = r & 7;
    g_bXt[idx] = pack_b1(in[(((size_t)b * TT + t) * NN + n) * F0 + f]);
}

// ---------------- dual sparse prop (bf16, fp32 accum), warp per node ---------
template<int VX, bool CHEB2, int SX, int DX, int TX, int SH, int DH, int TH>
__global__ void __launch_bounds__(256) k_prop2() {
    const unsigned short* __restrict__ xx  = bbufp(SX);
    unsigned short* __restrict__ yx        = bbufp(DX);
    const unsigned short* __restrict__ t0x = bbufp(TX);
    const uint2* __restrict__ xh   = (const uint2*)bbufp(SH);
    uint2* __restrict__ yh         = (uint2*)bbufp(DH);
    const uint2* __restrict__ t0h  = (const uint2*)bbufp(TH);
    const uint2* xxu = (const uint2*)xx;

    int wid = (blockIdx.x * blockDim.x + threadIdx.x) >> 5;
    int lane = threadIdx.x & 31;
    if (wid >= NN) return;
    int n = wid;
    int s = g_rowptr[n], e = g_rowptr[n + 1];

    float accx = 0.f;
    float4 accx4 = make_float4(0.f, 0.f, 0.f, 0.f);
    float4 acch = make_float4(0.f, 0.f, 0.f, 0.f);

    int i = s;
    for (; i + 2 <= e; i += 2) {
        int s0 = g_src[i], s1 = g_src[i + 1];
        float n0 = g_norm[i], n1 = g_norm[i + 1];
        uint2 h0 = xh[s0 * 32 + lane];
        uint2 h1 = xh[s1 * 32 + lane];
        if (VX == 32) {
            float a = bf2f(xx[s0 * 32 + lane]);
            float b = bf2f(xx[s1 * 32 + lane]);
            accx = fmaf(n0, a, accx);
            accx = fmaf(n1, b, accx);
        } else {
            uint2 a = xxu[s0 * 32 + lane];
            uint2 b = xxu[s1 * 32 + lane];
            fma_b4(accx4, n0, a);
            fma_b4(accx4, n1, b);
        }
        fma_b4(acch, n0, h0);
        fma_b4(acch, n1, h1);
    }
    for (; i < e; i++) {
        int s0 = g_src[i];
        float n0 = g_norm[i];
        uint2 h0 = xh[s0 * 32 + lane];
        if (VX == 32) {
            accx = fmaf(n0, bf2f(xx[s0 * 32 + lane]), accx);
        } else {
            uint2 a = xxu[s0 * 32 + lane];
            fma_b4(accx4, n0, a);
        }
        fma_b4(acch, n0, h0);
    }
    float d = g_diag[n];
    {
        fma_b4(acch, d, xh[n * 32 + lane]);
        if (CHEB2) {
            float4 tv = unpack_b4(t0h[n * 32 + lane]);
            acch.x = 2.f * acch.x - tv.x;
            acch.y = 2.f * acch.y - tv.y;
            acch.z = 2.f * acch.z - tv.z;
            acch.w = 2.f * acch.w - tv.w;
        }
        yh[n * 32 + lane] = pack_b4(acch);
    }
    if (VX == 32) {
        accx = fmaf(d, bf2f(xx[n * 32 + lane]), accx);
        if (CHEB2) accx = 2.f * accx - bf2f(t0x[n * 32 + lane]);
        yx[n * 32 + lane] = pack_b1(accx);
    } else {
        fma_b4(accx4, d, xxu[n * 32 + lane]);
        if (CHEB2) {
            float4 tv = unpack_b4(((const uint2*)t0x)[n * 32 + lane]);
            accx4.x = 2.f * accx4.x - tv.x;
            accx4.y = 2.f * accx4.y - tv.y;
            accx4.z = 2.f * accx4.z - tv.z;
            accx4.w = 2.f * accx4.w - tv.w;
        }
        ((uint2*)yx)[n * 32 + lane] = pack_b4(accx4);
    }
}

// ---------------- single sparse prop, 128-wide (HR chain), unroll x4 ---------
template<bool CHEB2, int SRC, int DST, int T0ID>
__global__ void __launch_bounds__(256) k_prop() {
    const uint2* __restrict__ x  = (const uint2*)bbufp(SRC);
    uint2* __restrict__ y        = (uint2*)bbufp(DST);
    const uint2* __restrict__ t0 = (const uint2*)bbufp(T0ID);
    int wid = (blockIdx.x * blockDim.x + threadIdx.x) >> 5;
    int lane = threadIdx.x & 31;
    if (wid >= NN) return;
    int n = wid;
    int s = g_rowptr[n], e = g_rowptr[n + 1];
    float4 acc = make_float4(0.f, 0.f, 0.f, 0.f);
    int i = s;
    for (; i + 4 <= e; i += 4) {
        int s0 = g_src[i], s1 = g_src[i + 1], s2 = g_src[i + 2], s3 = g_src[i + 3];
        float n0 = g_norm[i], n1 = g_norm[i + 1], n2 = g_norm[i + 2], n3 = g_norm[i + 3];
        uint2 v0 = x[s0 * 32 + lane];
        uint2 v1 = x[s1 * 32 + lane];
        uint2 v2 = x[s2 * 32 + lane];
        uint2 v3 = x[s3 * 32 + lane];
        fma_b4(acc, n0, v0);
        fma_b4(acc, n1, v1);
        fma_b4(acc, n2, v2);
        fma_b4(acc, n3, v3);
    }
    for (; i < e; i++) {
        uint2 v = x[g_src[i] * 32 + lane];
        fma_b4(acc, g_norm[i], v);
    }
    fma_b4(acc, g_diag[n], x[n * 32 + lane]);
    if (CHEB2) {
        float4 tv = unpack_b4(t0[n * 32 + lane]);
        acc.x = 2.f * acc.x - tv.x;
        acc.y = 2.f * acc.y - tv.y;
        acc.z = 2.f * acc.z - tv.z;
        acc.w = 2.f * acc.w - tv.w;
    }
    y[n * 32 + lane] = pack_b4(acc);
}

// ---------------- single sparse prop, 32-wide (layer-0 X chain), unroll x4 ---
template<bool CHEB2, int SRC, int DST, int T0ID>
__global__ void __launch_bounds__(256) k_prop1() {
    const unsigned short* __restrict__ x  = bbufp(SRC);
    unsigned short* __restrict__ y        = bbufp(DST);
    const unsigned short* __restrict__ t0 = bbufp(T0ID);
    int wid = (blockIdx.x * blockDim.x + threadIdx.x) >> 5;
    int lane = threadIdx.x & 31;
    if (wid >= NN) return;
    int n = wid;
    int s = g_rowptr[n], e = g_rowptr[n + 1];
    float acc = 0.f;
    int i = s;
    for (; i + 4 <= e; i += 4) {
        int s0 = g_src[i], s1 = g_src[i + 1], s2 = g_src[i + 2], s3 = g_src[i + 3];
        float n0 = g_norm[i], n1 = g_norm[i + 1], n2 = g_norm[i + 2], n3 = g_norm[i + 3];
        float v0 = bf2f(x[s0 * 32 + lane]);
        float v1 = bf2f(x[s1 * 32 + lane]);
        float v2 = bf2f(x[s2 * 32 + lane]);
        float v3 = bf2f(x[s3 * 32 + lane]);
        acc = fmaf(n0, v0, acc);
        acc = fmaf(n1, v1, acc);
        acc = fmaf(n2, v2, acc);
        acc = fmaf(n3, v3, acc);
    }
    for (; i < e; i++) acc = fmaf(g_norm[i], bf2f(x[g_src[i] * 32 + lane]), acc);
    acc = fmaf(g_diag[n], bf2f(x[n * 32 + lane]), acc);
    if (CHEB2) acc = 2.f * acc - bf2f(t0[n * 32 + lane]);
    y[n * 32 + lane] = pack_b1(acc);
}

// ================= einsums: R14 shape (p=4/warp, 16 pairs/block) =============

// ---------------- gx = sum_k TXk @ Wx[g,k] + bx[g]  (3 gates) ----------------
template<int FIN, int T0ID, int T1ID, int T2ID>
__global__ void k_gx(const float* __restrict__ W,   // [3][3][FIN][32]
                     const float* __restrict__ bx)  // [3][32]
{
    const unsigned short* __restrict__ T0 = bbufp(T0ID);
    const unsigned short* __restrict__ T1 = bbufp(T1ID);
    const unsigned short* __restrict__ T2 = bbufp(T2ID);
    __shared__ float Ws[9 * FIN * 32];
    __shared__ float Xs[3][16 * FIN];
    int tid = threadIdx.x;
    for (int i = tid; i < 9 * FIN * 32; i += 128) Ws[i] = W[i];
    int pb = blockIdx.x * 16;
    for (int i = tid; i < 16 * FIN; i += 128) {
        int idx = pb * FIN + i;
        Xs[0][i] = bf2f(T0[idx]);
        Xs[1][i] = bf2f(T1[idx]);
        Xs[2][i] = bf2f(T2[idx]);
    }
    __syncthreads();
    int warp = tid >> 5, lane = tid & 31;
    float a0[4], a1[4], a2[4];
#pragma unroll
    for (int p = 0; p < 4; p++) { a0[p] = bx[lane]; a1[p] = bx[32 + lane]; a2[p] = bx[64 + lane]; }
#pragma unroll
    for (int k = 0; k < 3; k++) {
#pragma unroll 4
        for (int i = 0; i < FIN; i++) {
            float w0 = Ws[((0 * 3 + k) * FIN + i) * 32 + lane];
            float w1 = Ws[((1 * 3 + k) * FIN + i) * 32 + lane];
            float w2 = Ws[((2 * 3 + k) * FIN + i) * 32 + lane];
#pragma unroll
            for (int p = 0; p < 4; p++) {
                float xv = Xs[k][(warp * 4 + p) * FIN + i];
                a0[p] = fmaf(xv, w0, a0[p]);
                a1[p] = fmaf(xv, w1, a1[p]);
                a2[p] = fmaf(xv, w2, a2[p]);
            }
        }
    }
#pragma unroll
    for (int p = 0; p < 4; p++) {
        size_t pair = pb + warp * 4 + p;
        g_gx[pair * 96 + lane]      = a0[p];
        g_gx[pair * 96 + 32 + lane] = a1[p];
        g_gx[pair * 96 + 64 + lane] = a2[p];
    }
}

// ---------------- Z/R gates + H*R (H from fp32 master, basis by buffer id) ---
template<int M, int T1ID, int T2ID>   // M: 0 -> H0, 1 -> H1
__global__ void k_gates(const float* __restrict__ Wh,  // [2][3][32][32]
                        const float* __restrict__ bh)  // [2][32]
{
    const float* __restrict__ H = (M == 0) ? g_H0 : g_H1;
    const unsigned short* __restrict__ B1 = bbufp(T1ID);
    const unsigned short* __restrict__ B2 = bbufp(T2ID);
    __shared__ float Ws[6144];
    __shared__ float Xs[3][512];
    int tid = threadIdx.x;
    for (int i = tid; i < 6144; i += 128) Ws[i] = Wh[i];
    int pb = blockIdx.x * 16;
    for (int i = tid; i < 512; i += 128) {
        int idx = pb * 32 + i;
        Xs[0][i] = H[idx];
        Xs[1][i] = bf2f(B1[idx]);
        Xs[2][i] = bf2f(B2[idx]);
    }
    __syncthreads();
    int warp = tid >> 5, lane = tid & 31;
    float az[4], ar[4];
#pragma unroll
    for (int p = 0; p < 4; p++) { az[p] = bh[lane]; ar[p] = bh[32 + lane]; }
#pragma unroll
    for (int k = 0; k < 3; k++) {
#pragma unroll 4
        for (int i = 0; i < 32; i++) {
            float w0 = Ws[(k * 32 + i) * 32 + lane];
            float w1 = Ws[3072 + (k * 32 + i) * 32 + lane];
#pragma unroll
            for (int p = 0; p < 4; p++) {
                float xv = Xs[k][(warp * 4 + p) * 32 + i];
                az[p] = fmaf(xv, w0, az[p]);
                ar[p] = fmaf(xv, w1, ar[p]);
            }
        }
    }
#pragma unroll
    for (int p = 0; p < 4; p++) {
        size_t pair = pb + warp * 4 + p;
        float z = 1.f / (1.f + expf(-(g_gx[pair * 96 + lane] + az[p])));
        float r = 1.f / (1.f + expf(-(g_gx[pair * 96 + 32 + lane] + ar[p])));
        float hv = Xs[0][(warp * 4 + p) * 32 + lane];
        g_Z[pair * 32 + lane] = z;
        g_bHR[pair * 32 + lane] = pack_b1(hv * r);
    }
}

// ---------------- candidate + blend (fp32 master in place + bf16 shadow) -----
template<int M>   // 0 -> H0, 1 -> H1
__global__ void k_final(const float* __restrict__ Wh2,  // [3][32][32]
                        const float* __restrict__ bh2)  // [32]
{
    float* __restrict__ Hst = (M == 0) ? g_H0 : g_H1;
    unsigned short* __restrict__ Hsh = (M == 0) ? g_bH0 : g_bH1;
    __shared__ float Ws[3072];
    __shared__ float Xs[3][512];
    int tid = threadIdx.x;
    for (int i = tid; i < 3072; i += 128) Ws[i] = Wh2[i];
    int pb = blockIdx.x * 16;
    for (int i = tid; i < 512; i += 128) {
        int idx = pb * 32 + i;
        Xs[0][i] = bf2f(g_bHR[idx]);
        Xs[1][i] = bf2f(g_bT1[idx]);
        Xs[2][i] = bf2f(g_bT2[idx]);
    }
    __syncthreads();
    int warp = tid >> 5, lane = tid & 31;
    float acc[4];
#pragma unroll
    for (int p = 0; p < 4; p++) acc[p] = bh2[lane];
#pragma unroll
    for (int k = 0; k < 3; k++) {
#pragma unroll 4
        for (int i = 0; i < 32; i++) {
            float w = Ws[(k * 32 + i) * 32 + lane];
#pragma unroll
            for (int p = 0; p < 4; p++) {
                float xv = Xs[k][(warp * 4 + p) * 32 + i];
                acc[p] = fmaf(xv, w, acc[p]);
            }
        }
    }
#pragma unroll
    for (int p = 0; p < 4; p++) {
        size_t pair = pb + warp * 4 + p;
        float ht = tanhf(g_gx[pair * 96 + 64 + lane] + acc[p]);
        float z = g_Z[pair * 32 + lane];
        float h = Hst[pair * 32 + lane];   // read own element, then overwrite
        float hn = z * h + (1.f - z) * ht;
        Hst[pair * 32 + lane] = hn;
        Hsh[pair * 32 + lane] = pack_b1(hn);
    }
}

// ---------------- output head (fp32 master) ----------------------------------
__global__ void k_head(const float* __restrict__ muW, const float* __restrict__ mub,
                       const float* __restrict__ sgW, const float* __restrict__ sgb,
                       float* __restrict__ out) {
    int gtid = blockIdx.x * blockDim.x + threadIdx.x;
    int pair = gtid >> 5, lane = gtid & 31;
    if (pair >= NP) return;
    float v = g_H1[pair * 32 + lane];
    float m0 = v * muW[lane * 2 + 0];
    float m1 = v * muW[lane * 2 + 1];
    float s0 = v * sgW[lane * 2 + 0];
    float s1 = v * sgW[lane * 2 + 1];
#pragma unroll
    for (int o = 16; o > 0; o >>= 1) {
        m0 += __shfl_xor_sync(0xffffffffu, m0, o);
        m1 += __shfl_xor_sync(0xffffffffu, m1, o);
        s0 += __shfl_xor_sync(0xffffffffu, s0, o);
        s1 += __shfl_xor_sync(0xffffffffu, s1, o);
    }
    if (lane == 0) {
        int n = pair >> 2, b = pair & 3;
        float mu0 = 1.f / (1.f + expf(-(m0 + mub[0])));
        float mu1 = 1.f / (1.f + expf(-(m1 + mub[1])));
        float x0 = s0 + sgb[0], x1 = s1 + sgb[1];
        float sg0 = (x0 > 20.f) ? x0 : log1pf(expf(x0));
        float sg1 = (x1 > 20.f) ? x1 : log1pf(expf(x1));
        size_t o0 = ((size_t)b * NN + n) * 2;
        out[o0] = mu0;
        out[o0 + 1] = mu1;
        out[2 * (size_t)NN * BB + o0] = sg0;
        out[2 * (size_t)NN * BB + o0 + 1] = sg1;
    }
}

__global__ void k_mean() {
    int b = blockIdx.x;
    int h = threadIdx.x & 31;
    int grp = threadIdx.x >> 5;      // 8 groups
    float s = 0.f;
    for (int n = grp; n < NN; n += 8) s += g_H1[(size_t)n * 128 + b * 32 + h];
    __shared__ float sh[8][32];
    sh[grp][h] = s;
    __syncthreads();
    if (grp == 0) {
#pragma unroll
        for (int r = 1; r < 8; r++) s += sh[r][h];
        g_mean[b * 32 + h] = s / (float)NN;
    }
}

__global__ void k_soft(float* __restrict__ out) {
    int b = threadIdx.x >> 5, h = threadIdx.x & 31;
    float v = g_mean[b * 32 + h];
    float m = v;
#pragma unroll
    for (int o = 16; o > 0; o >>= 1) m = fmaxf(m, __shfl_xor_sync(0xffffffffu, m, o));
    float e = expf(v - m);
    float s = e;
#pragma unroll
    for (int o = 16; o > 0; o >>= 1) s += __shfl_xor_sync(0xffffffffu, s, o);
    out[4 * (size_t)NN * BB + b * 32 + h] = e / s;
}

// ---------------- host orchestration (kernel launches ONLY) -------------------
extern "C" void kernel_launch(void* const* d_in, const int* in_sizes, int n_in,
                              void* d_out, int out_size) {
    const float* in_tensor = (const float*)d_in[0];
    const void*  edge_ix   = d_in[1];
    const float* edge_w    = (const float*)d_in[2];
    const float* Wx0 = (const float*)d_in[3];
    const float* Wh0 = (const float*)d_in[4];
    const float* bx0 = (const float*)d_in[5];
    const float* bh0 = (const float*)d_in[6];
    const float* Wx1 = (const float*)d_in[7];
    const float* Wh1 = (const float*)d_in[8];
    const float* bx1 = (const float*)d_in[9];
    const float* bh1 = (const float*)d_in[10];
    const float* muW = (const float*)d_in[11];
    const float* mub = (const float*)d_in[12];
    const float* sgW = (const float*)d_in[13];
    const float* sgb = (const float*)d_in[14];
    float* out = (float*)d_out;

    k_init<<<(NN * BH + 255) / 256, 256>>>((const int*)edge_ix);
    k_degcnt<<<(EE + 255) / 256, 256>>>(edge_ix, edge_w);
    k_scan<<<1, 1024>>>();
    k_scatter<<<(EE + 255) / 256, 256>>>(edge_ix, edge_w);

    const int PGRID = NN / 8;    // 6250 blocks * 256 thr = warp per node
    const int EGRID = NP / 16;   // 12500 blocks * 128 thr = 16 pairs/block

    // buffer ids: 0=Xt 1=T1 2=T2 3=H0 4=H1 5=HR 6=U1 7=U2 8=XA 9=XB
    for (int t = 0; t < TT; t++) {
        // ---- layer 0 (state H0, input Xt) ----
        // H0-basis is REUSED from previous step's layer-1 prop2 (lives in U1/U2;
        // zeros at t=0 == basis of H0=0). Only the cheap 32-wide X chain runs here.
        k_transpose<<<(NN * 32 + 255) / 256, 256>>>(in_tensor, t);
        k_prop1<false, 0, 8, 0><<<PGRID, 256>>>();               // Xt->XA
        k_prop1<true,  8, 9, 0><<<PGRID, 256>>>();               // XA->XB (t0=Xt)
        k_gx<8, 0, 8, 9><<<EGRID, 128>>>(Wx0, bx0);
        k_gates<0, 6, 7><<<EGRID, 128>>>(Wh0, bh0);              // basis(H0) from U1/U2
        k_prop<false, 5, 1, 5><<<PGRID, 256>>>();                // HR->T1
        k_prop<true,  1, 2, 5><<<PGRID, 256>>>();                // T1->T2 (t0=HR)
        k_final<0><<<EGRID, 128>>>(Wh0 + 2 * 3 * 32 * 32, bh0 + 64);

        // ---- layer 1 (state H1, input = freshly updated H0) ----
        // prop2 computes basis(H0_new) into U1/U2 (used now by k_gx AND next step's
        // layer-0 gates) and basis(H1) into T1/T2.
        k_prop2<128, false, 3, 6, 3, 4, 1, 4><<<PGRID, 256>>>();  // H0->U1 | H1->T1
        k_prop2<128, true,  6, 7, 3, 1, 2, 4><<<PGRID, 256>>>();  // U1->U2 (t0=H0) | T1->T2 (t0=H1)
        k_gx<32, 3, 6, 7><<<EGRID, 128>>>(Wx1, bx1);
        k_gates<1, 1, 2><<<EGRID, 128>>>(Wh1, bh1);               // basis(H1) from T1/T2
        k_prop<false, 5, 1, 5><<<PGRID, 256>>>();
        k_prop<true,  1, 2, 5><<<PGRID, 256>>>();
        k_final<1><<<EGRID, 128>>>(Wh1 + 2 * 3 * 32 * 32, bh1 + 64);
    }

    k_head<<<NP / 8, 256>>>(muW, mub, sgW, sgb, out);
    k_mean<<<BB, 256>>>();
    k_soft<<<1, 128>>>(out);
}